// round 15
// baseline (speedup 1.0000x reference)
#include <cuda_runtime.h>
#include <cuda_bf16.h>
#include <cstdint>
#include <cstddef>

// ---------------------------------------------------------------------------
// BitNet FFN, round 15: round-14 structure (best, 1434.3us). Single change:
// k_hquant moves to 512 threads/block (same strided coalesced pattern, half
// the per-thread erf chain, 2x warps to interleave FMA with loads).
// Arithmetic per element identical; block-max order-independent -> bit-exact.
// ---------------------------------------------------------------------------

#define EPSQ 1e-5f
#define TOKENS   8192
#define DMODEL   2048
#define DHIDDEN  8192

// ------------------------- device scratch (no allocs) ----------------------
__device__ float                        g_partial[4096];
__device__ float                        g_scales[2];
__device__ __align__(16) __nv_bfloat16  g_w1q[(size_t)DHIDDEN * DMODEL];
__device__ __align__(16) __nv_bfloat16  g_w2q[(size_t)DMODEL * DHIDDEN];
__device__ __align__(16) __nv_bfloat16  g_xq [(size_t)TOKENS * DMODEL];
__device__ float                        g_xscale[TOKENS];
__device__ __align__(16) float          g_c1 [(size_t)TOKENS * DHIDDEN];
__device__ __align__(16) __nv_bfloat16  g_hq [(size_t)TOKENS * DHIDDEN];
__device__ float                        g_hscale[TOKENS];

// ------------------------------- helpers -----------------------------------
__device__ __forceinline__ float gelu_exact(float v) {
    return 0.5f * v * (1.0f + erff(v * 0.70710678118654752440f));
}
__device__ __forceinline__ float q_act(float v, float s) {
    return fminf(fmaxf(rintf(v * s), -128.0f), 127.0f);
}
__device__ __forceinline__ float q_w(float v, float s) {
    return fminf(fmaxf(rintf(v * s), -1.0f), 1.0f);
}
__device__ __forceinline__ uint32_t pack_bf2(float a, float b) {
    __nv_bfloat162 h = __floats2bfloat162_rn(a, b);
    return *reinterpret_cast<uint32_t*>(&h);
}
__device__ __forceinline__ uint32_t smem_u32(const void* p) {
    return (uint32_t)__cvta_generic_to_shared(p);
}
__device__ __forceinline__ void ldm_x4(uint32_t* r, uint32_t addr) {
    asm volatile("ldmatrix.sync.aligned.m8n8.x4.shared.b16 {%0,%1,%2,%3}, [%4];"
                 : "=r"(r[0]), "=r"(r[1]), "=r"(r[2]), "=r"(r[3]) : "r"(addr));
}
__device__ __forceinline__ void mma16816(float* d, const uint32_t* a, const uint32_t* b) {
    asm volatile("mma.sync.aligned.m16n8k16.row.col.f32.bf16.bf16.f32 "
                 "{%0,%1,%2,%3}, {%4,%5,%6,%7}, {%8,%9}, {%0,%1,%2,%3};"
                 : "+f"(d[0]), "+f"(d[1]), "+f"(d[2]), "+f"(d[3])
                 : "r"(a[0]), "r"(a[1]), "r"(a[2]), "r"(a[3]),
                   "r"(b[0]), "r"(b[1]));
}
#define CP_ASYNC16(dst, src) \
    asm volatile("cp.async.cg.shared.global [%0], [%1], 16;" :: "r"(dst), "l"(src) : "memory")
#define CP_COMMIT() asm volatile("cp.async.commit_group;" ::: "memory")
#define CP_WAIT(n)  asm volatile("cp.async.wait_group %0;" :: "n"(n) : "memory")
// SW128 swizzle on byte offset within a 128B-row tile (Swizzle<3,4,3>)
#define SW(o) ((o) ^ (((o) >> 3) & 0x70))

// warp-level reductions (max is order-independent -> bit-exact)
__device__ __forceinline__ float warp_max(float v) {
    #pragma unroll
    for (int o = 16; o > 0; o >>= 1)
        v = fmaxf(v, __shfl_xor_sync(0xffffffffu, v, o));
    return v;
}
__device__ __forceinline__ float warp_sum(float v) {
    #pragma unroll
    for (int o = 16; o > 0; o >>= 1)
        v += __shfl_xor_sync(0xffffffffu, v, o);
    return v;
}
// NW-warp block max with a single barrier (order-independent, bit-exact)
template <int NW>
__device__ __forceinline__ float block_max(float v, int tid) {
    __shared__ float wred[NW];
    float wm = warp_max(v);
    if ((tid & 31) == 0) wred[tid >> 5] = wm;
    __syncthreads();
    float m = wred[0];
    #pragma unroll
    for (int i = 1; i < NW; i++) m = fmaxf(m, wred[i]);
    return m;
}

// -------------- K0: |w| partial sums for ONE matrix (float4) ----------------
template <int IDX>
__global__ void k_wsum(const float* __restrict__ w) {
    int b = blockIdx.x;
    const float4* wv = reinterpret_cast<const float4*>(w + (size_t)b * 8192);
    float s = 0.0f;
    #pragma unroll
    for (int i = 0; i < 8; i++) {
        float4 v = wv[threadIdx.x + i * 256];
        s += fabsf(v.x) + fabsf(v.y) + fabsf(v.z) + fabsf(v.w);
    }
    __shared__ float wred[8];
    float ws = warp_sum(s);
    if ((threadIdx.x & 31) == 0) wred[threadIdx.x >> 5] = ws;
    __syncthreads();
    if (threadIdx.x == 0) {
        float t = wred[0];
        #pragma unroll
        for (int i = 1; i < 8; i++) t += wred[i];
        g_partial[IDX * 2048 + b] = t;
    }
}

// -------------- K0b: finalize scale for ONE matrix --------------------------
template <int IDX>
__global__ void k_scale() {
    __shared__ float red[256];
    float s = 0.0f;
    for (int i = threadIdx.x; i < 2048; i += 256) s += g_partial[IDX * 2048 + i];
    red[threadIdx.x] = s; __syncthreads();
    for (int o = 128; o > 0; o >>= 1) {
        if (threadIdx.x < o) red[threadIdx.x] += red[threadIdx.x + o];
        __syncthreads();
    }
    if (threadIdx.x == 0) {
        float m = red[0] * (1.0f / 16777216.0f);
        g_scales[IDX] = 1.0f / fmaxf(m, EPSQ);
    }
}

// ---------------- K1: ternary-quantize one weight matrix --------------------
template <int IDX>
__global__ void k_wquant(const float* __restrict__ w) {
    __nv_bfloat16* o = (IDX == 0) ? g_w1q : g_w2q;
    float s = g_scales[IDX];
    size_t idx = ((size_t)blockIdx.x * 256 + threadIdx.x) * 8;
    float4 v0 = *reinterpret_cast<const float4*>(w + idx);
    float4 v1 = *reinterpret_cast<const float4*>(w + idx + 4);
    uint4 out;
    out.x = pack_bf2(q_w(v0.x, s), q_w(v0.y, s));
    out.y = pack_bf2(q_w(v0.z, s), q_w(v0.w, s));
    out.z = pack_bf2(q_w(v1.x, s), q_w(v1.y, s));
    out.w = pack_bf2(q_w(v1.z, s), q_w(v1.w, s));
    *reinterpret_cast<uint4*>(o + idx) = out;
}

// ------------------------- K2: per-token int8 quant of x --------------------
__global__ void k_xquant(const float* __restrict__ x) {
    int m = blockIdx.x, tid = threadIdx.x;
    const float4* row = reinterpret_cast<const float4*>(x + (size_t)m * DMODEL);
    float4 v0 = row[tid], v1 = row[tid + 256];
    float amax = fmaxf(fmaxf(fmaxf(fabsf(v0.x), fabsf(v0.y)), fmaxf(fabsf(v0.z), fabsf(v0.w))),
                       fmaxf(fmaxf(fabsf(v1.x), fabsf(v1.y)), fmaxf(fabsf(v1.z), fabsf(v1.w))));
    float m8 = block_max<8>(amax, tid);
    float scale = 127.0f / fmaxf(m8, EPSQ);
    uint2 o0, o1;
    o0.x = pack_bf2(q_act(v0.x, scale), q_act(v0.y, scale));
    o0.y = pack_bf2(q_act(v0.z, scale), q_act(v0.w, scale));
    o1.x = pack_bf2(q_act(v1.x, scale), q_act(v1.y, scale));
    o1.y = pack_bf2(q_act(v1.z, scale), q_act(v1.w, scale));
    uint2* orow = reinterpret_cast<uint2*>(g_xq + (size_t)m * DMODEL);
    orow[tid] = o0;
    orow[tid + 256] = o1;
    if (tid == 0) g_xscale[m] = scale;
}

// ------------------- K4: dequant + gelu + row requant (512 thr) -------------
// Same strided coalesced pattern as round 6/14, half the per-thread erf chain.
__global__ void k_hquant() {
    int m = blockIdx.x, tid = threadIdx.x;
    const float4* crow = reinterpret_cast<const float4*>(g_c1 + (size_t)m * DHIDDEN);
    float f = 1.0f / (g_xscale[m] * g_scales[0]);
    float gv[16];
    float amax = 0.0f;
    #pragma unroll
    for (int j = 0; j < 4; j++) {
        float4 v = crow[tid + j * 512];
        float a = gelu_exact(v.x * f), b = gelu_exact(v.y * f);
        float c = gelu_exact(v.z * f), d = gelu_exact(v.w * f);
        gv[j * 4 + 0] = a; gv[j * 4 + 1] = b; gv[j * 4 + 2] = c; gv[j * 4 + 3] = d;
        amax = fmaxf(amax, fmaxf(fmaxf(fabsf(a), fabsf(b)), fmaxf(fabsf(c), fabsf(d))));
    }
    float m16 = block_max<16>(amax, tid);
    float scale = 127.0f / fmaxf(m16, EPSQ);
    uint2* orow = reinterpret_cast<uint2*>(g_hq + (size_t)m * DHIDDEN);
    #pragma unroll
    for (int j = 0; j < 4; j++) {
        uint2 o;
        o.x = pack_bf2(q_act(gv[j * 4 + 0], scale), q_act(gv[j * 4 + 1], scale));
        o.y = pack_bf2(q_act(gv[j * 4 + 2], scale), q_act(gv[j * 4 + 3], scale));
        orow[tid + j * 512] = o;
    }
    if (tid == 0) g_hscale[m] = scale;
}

// =================== bf16 GEMM: C = A(MxK) * B(NxK)^T (fp32 accum) ==========
// CTA tile 128x128, K-step 64 bf16 (128B rows, SW128 swizzle),
// cp.async 3-stage pipeline, 8 warps (4M x 2N), warp tile 32x64.
// (byte-for-byte the round-6 kernel — proven local optimum)
template <int KDIM, int MODE>
__global__ void __launch_bounds__(256, 2) k_gemm_bf(float* __restrict__ Cout) {
    constexpr int TM = 128, TN = 128, KSTEP = 64, STAGES = 3;
    constexpr int KT = KDIM / KSTEP;
    constexpr int TILE_BYTES = TM * 128;        // 16 KB (128 rows x 128B)

    extern __shared__ __align__(1024) char smem[];

    const __nv_bfloat16* __restrict__ A = (MODE == 0) ? g_xq  : g_hq;
    const __nv_bfloat16* __restrict__ B = (MODE == 0) ? g_w1q : g_w2q;

    const int tid = threadIdx.x, warp = tid >> 5, lane = tid & 31;
    const int mblock = blockIdx.y * TM;
    const int nblock = blockIdx.x * TN;
    const int wm = (warp >> 1) * 32;       // 4 warps along M
    const int wn = (warp & 1) * 64;        // 2 warps along N

    const uint32_t a_base = smem_u32(smem);
    const uint32_t b_base = a_base + STAGES * TILE_BYTES;

    // ldmatrix lane geometry (byte offsets within 128B-row tile)
    const int aRow = wm + (lane & 15);
    const int bRow = wn + (lane & 15);
    const int colB = (lane >> 4) * 16;     // 16B sub-column

    float acc[2][8][4];
    #pragma unroll
    for (int i = 0; i < 2; i++)
        #pragma unroll
        for (int j = 0; j < 8; j++)
            #pragma unroll
            for (int k = 0; k < 4; k++) acc[i][j][k] = 0.0f;

    // per-thread cp.async geometry: 1024 16B chunks per matrix per stage
    auto load_stage = [&](int kt, int buf) {
        #pragma unroll
        for (int i = 0; i < 4; i++) {
            int c = tid + i * 256;
            int row = c >> 3, ch = c & 7;
            uint32_t swo = SW((uint32_t)(row * 128 + ch * 16));
            const char* asrc = (const char*)A + (size_t)(mblock + row) * (KDIM * 2) + kt * 128 + ch * 16;
            const char* bsrc = (const char*)B + (size_t)(nblock + row) * (KDIM * 2) + kt * 128 + ch * 16;
            CP_ASYNC16(a_base + buf * TILE_BYTES + swo, asrc);
            CP_ASYNC16(b_base + buf * TILE_BYTES + swo, bsrc);
        }
    };

    // prologue: stages 0,1
    load_stage(0, 0); CP_COMMIT();
    load_stage(1, 1); CP_COMMIT();

    for (int kt = 0; kt < KT; kt++) {
        CP_WAIT(1);
        __syncthreads();

        const int nk = kt + 2;
        if (nk < KT) load_stage(nk, nk % STAGES);
        CP_COMMIT();

        const uint32_t abase = a_base + (kt % STAGES) * TILE_BYTES;
        const uint32_t bbase = b_base + (kt % STAGES) * TILE_BYTES;
        #pragma unroll
        for (int kk = 0; kk < 4; kk++) {           // 4 x K=16 per stage
            uint32_t af[2][4], bf[8][2];
            #pragma unroll
            for (int mt = 0; mt < 2; mt++)
                ldm_x4(af[mt], abase + SW((uint32_t)((aRow + mt * 16) * 128 + kk * 32 + colB)));
            #pragma unroll
            for (int p = 0; p < 4; p++) {          // each x4 covers 2 n-tiles
                uint32_t r[4];
                ldm_x4(r, bbase + SW((uint32_t)((bRow + p * 16) * 128 + kk * 32 + colB)));
                bf[p*2][0]   = r[0]; bf[p*2][1]   = r[2];
                bf[p*2+1][0] = r[1]; bf[p*2+1][1] = r[3];
            }
            #pragma unroll
            for (int mt = 0; mt < 2; mt++)
                #pragma unroll
                for (int nt = 0; nt < 8; nt++)
                    mma16816(acc[mt][nt], af[mt], bf[nt]);
        }
    }

    // ---- epilogue ----
    const int gq = lane >> 2;
    const int tc = (lane & 3) * 2;
    #pragma unroll
    for (int mt = 0; mt < 2; mt++) {
        const int m0 = mblock + wm + mt * 16 + gq;
        float inv0 = 1.0f, inv1 = 1.0f;
        if (MODE == 1) {
            inv0 = 1.0f / (g_hscale[m0]     * g_scales[1]);
            inv1 = 1.0f / (g_hscale[m0 + 8] * g_scales[1]);
        }
        #pragma unroll
        for (int nt = 0; nt < 8; nt++) {
            const int n0 = nblock + wn + nt * 8 + tc;
            if (MODE == 0) {
                float2 v0 = make_float2(acc[mt][nt][0], acc[mt][nt][1]);
                float2 v1 = make_float2(acc[mt][nt][2], acc[mt][nt][3]);
                *reinterpret_cast<float2*>(&g_c1[(size_t)m0 * DHIDDEN + n0])       = v0;
                *reinterpret_cast<float2*>(&g_c1[(size_t)(m0 + 8) * DHIDDEN + n0]) = v1;
            } else {
                float2 v0 = make_float2(acc[mt][nt][0] * inv0, acc[mt][nt][1] * inv0);
                float2 v1 = make_float2(acc[mt][nt][2] * inv1, acc[mt][nt][3] * inv1);
                *reinterpret_cast<float2*>(&Cout[(size_t)m0 * DMODEL + n0])       = v0;
                *reinterpret_cast<float2*>(&Cout[(size_t)(m0 + 8) * DMODEL + n0]) = v1;
            }
        }
    }
}

// ------------------------------- launch -------------------------------------
extern "C" void kernel_launch(void* const* d_in, const int* in_sizes, int n_in,
                              void* d_out, int out_size) {
    const float* x  = (const float*)d_in[0];
    const float* w1 = (const float*)d_in[1];
    const float* w2 = (const float*)d_in[2];
    float* out = (float*)d_out;

    constexpr int SMEM_BYTES = 3 * 2 * 128 * 128;   // 96 KB dynamic
    cudaFuncSetAttribute(k_gemm_bf<DMODEL, 0>,
                         cudaFuncAttributeMaxDynamicSharedMemorySize, SMEM_BYTES);
    cudaFuncSetAttribute(k_gemm_bf<DHIDDEN, 1>,
                         cudaFuncAttributeMaxDynamicSharedMemorySize, SMEM_BYTES);

    // One-time side stream + events (host handles only, reused every call).
    static cudaStream_t s1 = nullptr;
    static cudaEvent_t ev_fork = nullptr, ev_xq = nullptr, ev_w2 = nullptr;
    if (s1 == nullptr) {
        cudaStreamCreateWithFlags(&s1, cudaStreamNonBlocking);
        cudaEventCreateWithFlags(&ev_fork, cudaEventDisableTiming);
        cudaEventCreateWithFlags(&ev_xq,   cudaEventDisableTiming);
        cudaEventCreateWithFlags(&ev_w2,   cudaEventDisableTiming);
    }

    // side branch: xquant (independent), then the ENTIRE w2 chain — all of it
    // hides under the main branch's w1 chain + GEMM1.
    cudaEventRecord(ev_fork, 0);
    cudaStreamWaitEvent(s1, ev_fork, 0);
    k_xquant<<<TOKENS, 256, 0, s1>>>(x);
    cudaEventRecord(ev_xq, s1);
    k_wsum<1>  <<<2048, 256, 0, s1>>>(w2);
    k_scale<1> <<<1,    256, 0, s1>>>();
    k_wquant<1><<<8192, 256, 0, s1>>>(w2);
    cudaEventRecord(ev_w2, s1);

    // main branch: w1 chain only
    k_wsum<0>  <<<2048, 256>>>(w1);
    k_scale<0> <<<1,    256>>>();
    k_wquant<0><<<8192, 256>>>(w1);

    // join xquant, then GEMM1 -> hquant
    cudaStreamWaitEvent(0, ev_xq, 0);
    k_gemm_bf<DMODEL, 0><<<dim3(DHIDDEN / 128, TOKENS / 128), 256, SMEM_BYTES>>>(nullptr);
    k_hquant<<<TOKENS, 512>>>();

    // join w2 chain, then GEMM2
    cudaStreamWaitEvent(0, ev_w2, 0);
    k_gemm_bf<DHIDDEN, 1><<<dim3(DMODEL / 128, TOKENS / 128), 256, SMEM_BYTES>>>(out);
}

// round 16
// speedup vs baseline: 1.0189x; 1.0189x over previous
#include <cuda_runtime.h>
#include <cuda_bf16.h>
#include <cstdint>
#include <cstddef>

// ---------------------------------------------------------------------------
// BitNet FFN, round 16: byte-for-byte restore of round 14 — the proven best
// (1434.3us). bf16 HMMA GEMMs (CTA 128x128, 2 CTA/SM, cp.async 3-stage,
// SW128, K-step 64); per-matrix weight-scale chains on forked streams
// (w2 chain + xquant hidden under w1 chain + GEMM1); shuffle reductions.
// Integer-exact bf16 operands; fp32 accumulation.
// ---------------------------------------------------------------------------

#define EPSQ 1e-5f
#define TOKENS   8192
#define DMODEL   2048
#define DHIDDEN  8192

// ------------------------- device scratch (no allocs) ----------------------
__device__ float                        g_partial[4096];
__device__ float                        g_scales[2];
__device__ __align__(16) __nv_bfloat16  g_w1q[(size_t)DHIDDEN * DMODEL];
__device__ __align__(16) __nv_bfloat16  g_w2q[(size_t)DMODEL * DHIDDEN];
__device__ __align__(16) __nv_bfloat16  g_xq [(size_t)TOKENS * DMODEL];
__device__ float                        g_xscale[TOKENS];
__device__ __align__(16) float          g_c1 [(size_t)TOKENS * DHIDDEN];
__device__ __align__(16) __nv_bfloat16  g_hq [(size_t)TOKENS * DHIDDEN];
__device__ float                        g_hscale[TOKENS];

// ------------------------------- helpers -----------------------------------
__device__ __forceinline__ float gelu_exact(float v) {
    return 0.5f * v * (1.0f + erff(v * 0.70710678118654752440f));
}
__device__ __forceinline__ float q_act(float v, float s) {
    return fminf(fmaxf(rintf(v * s), -128.0f), 127.0f);
}
__device__ __forceinline__ float q_w(float v, float s) {
    return fminf(fmaxf(rintf(v * s), -1.0f), 1.0f);
}
__device__ __forceinline__ uint32_t pack_bf2(float a, float b) {
    __nv_bfloat162 h = __floats2bfloat162_rn(a, b);
    return *reinterpret_cast<uint32_t*>(&h);
}
__device__ __forceinline__ uint32_t smem_u32(const void* p) {
    return (uint32_t)__cvta_generic_to_shared(p);
}
__device__ __forceinline__ void ldm_x4(uint32_t* r, uint32_t addr) {
    asm volatile("ldmatrix.sync.aligned.m8n8.x4.shared.b16 {%0,%1,%2,%3}, [%4];"
                 : "=r"(r[0]), "=r"(r[1]), "=r"(r[2]), "=r"(r[3]) : "r"(addr));
}
__device__ __forceinline__ void mma16816(float* d, const uint32_t* a, const uint32_t* b) {
    asm volatile("mma.sync.aligned.m16n8k16.row.col.f32.bf16.bf16.f32 "
                 "{%0,%1,%2,%3}, {%4,%5,%6,%7}, {%8,%9}, {%0,%1,%2,%3};"
                 : "+f"(d[0]), "+f"(d[1]), "+f"(d[2]), "+f"(d[3])
                 : "r"(a[0]), "r"(a[1]), "r"(a[2]), "r"(a[3]),
                   "r"(b[0]), "r"(b[1]));
}
#define CP_ASYNC16(dst, src) \
    asm volatile("cp.async.cg.shared.global [%0], [%1], 16;" :: "r"(dst), "l"(src) : "memory")
#define CP_COMMIT() asm volatile("cp.async.commit_group;" ::: "memory")
#define CP_WAIT(n)  asm volatile("cp.async.wait_group %0;" :: "n"(n) : "memory")
// SW128 swizzle on byte offset within a 128B-row tile (Swizzle<3,4,3>)
#define SW(o) ((o) ^ (((o) >> 3) & 0x70))

// warp-level reductions (max is order-independent -> bit-exact)
__device__ __forceinline__ float warp_max(float v) {
    #pragma unroll
    for (int o = 16; o > 0; o >>= 1)
        v = fmaxf(v, __shfl_xor_sync(0xffffffffu, v, o));
    return v;
}
__device__ __forceinline__ float warp_sum(float v) {
    #pragma unroll
    for (int o = 16; o > 0; o >>= 1)
        v += __shfl_xor_sync(0xffffffffu, v, o);
    return v;
}
// 256-thread block max with a single barrier
__device__ __forceinline__ float block_max_256(float v, int tid) {
    __shared__ float wred[8];
    float wm = warp_max(v);
    if ((tid & 31) == 0) wred[tid >> 5] = wm;
    __syncthreads();
    float m = wred[0];
    #pragma unroll
    for (int i = 1; i < 8; i++) m = fmaxf(m, wred[i]);
    return m;
}

// -------------- K0: |w| partial sums for ONE matrix (float4) ----------------
// IDX 0: w1 -> g_partial[0..2047];  IDX 1: w2 -> g_partial[2048..4095]
template <int IDX>
__global__ void k_wsum(const float* __restrict__ w) {
    int b = blockIdx.x;
    const float4* wv = reinterpret_cast<const float4*>(w + (size_t)b * 8192);
    float s = 0.0f;
    #pragma unroll
    for (int i = 0; i < 8; i++) {
        float4 v = wv[threadIdx.x + i * 256];
        s += fabsf(v.x) + fabsf(v.y) + fabsf(v.z) + fabsf(v.w);
    }
    __shared__ float wred[8];
    float ws = warp_sum(s);
    if ((threadIdx.x & 31) == 0) wred[threadIdx.x >> 5] = ws;
    __syncthreads();
    if (threadIdx.x == 0) {
        float t = wred[0];
        #pragma unroll
        for (int i = 1; i < 8; i++) t += wred[i];
        g_partial[IDX * 2048 + b] = t;
    }
}

// -------------- K0b: finalize scale for ONE matrix --------------------------
template <int IDX>
__global__ void k_scale() {
    __shared__ float red[256];
    float s = 0.0f;
    for (int i = threadIdx.x; i < 2048; i += 256) s += g_partial[IDX * 2048 + i];
    red[threadIdx.x] = s; __syncthreads();
    for (int o = 128; o > 0; o >>= 1) {
        if (threadIdx.x < o) red[threadIdx.x] += red[threadIdx.x + o];
        __syncthreads();
    }
    if (threadIdx.x == 0) {
        float m = red[0] * (1.0f / 16777216.0f);
        g_scales[IDX] = 1.0f / fmaxf(m, EPSQ);
    }
}

// ---------------- K1: ternary-quantize one weight matrix --------------------
template <int IDX>
__global__ void k_wquant(const float* __restrict__ w) {
    __nv_bfloat16* o = (IDX == 0) ? g_w1q : g_w2q;
    float s = g_scales[IDX];
    size_t idx = ((size_t)blockIdx.x * 256 + threadIdx.x) * 8;
    float4 v0 = *reinterpret_cast<const float4*>(w + idx);
    float4 v1 = *reinterpret_cast<const float4*>(w + idx + 4);
    uint4 out;
    out.x = pack_bf2(q_w(v0.x, s), q_w(v0.y, s));
    out.y = pack_bf2(q_w(v0.z, s), q_w(v0.w, s));
    out.z = pack_bf2(q_w(v1.x, s), q_w(v1.y, s));
    out.w = pack_bf2(q_w(v1.z, s), q_w(v1.w, s));
    *reinterpret_cast<uint4*>(o + idx) = out;
}

// ------------------------- K2: per-token int8 quant of x --------------------
__global__ void k_xquant(const float* __restrict__ x) {
    int m = blockIdx.x, tid = threadIdx.x;
    const float4* row = reinterpret_cast<const float4*>(x + (size_t)m * DMODEL);
    float4 v0 = row[tid], v1 = row[tid + 256];
    float amax = fmaxf(fmaxf(fmaxf(fabsf(v0.x), fabsf(v0.y)), fmaxf(fabsf(v0.z), fabsf(v0.w))),
                       fmaxf(fmaxf(fabsf(v1.x), fabsf(v1.y)), fmaxf(fabsf(v1.z), fabsf(v1.w))));
    float m8 = block_max_256(amax, tid);
    float scale = 127.0f / fmaxf(m8, EPSQ);
    uint2 o0, o1;
    o0.x = pack_bf2(q_act(v0.x, scale), q_act(v0.y, scale));
    o0.y = pack_bf2(q_act(v0.z, scale), q_act(v0.w, scale));
    o1.x = pack_bf2(q_act(v1.x, scale), q_act(v1.y, scale));
    o1.y = pack_bf2(q_act(v1.z, scale), q_act(v1.w, scale));
    uint2* orow = reinterpret_cast<uint2*>(g_xq + (size_t)m * DMODEL);
    orow[tid] = o0;
    orow[tid + 256] = o1;
    if (tid == 0) g_xscale[m] = scale;
}

// ------------------------- K4: dequant + gelu + row requant -----------------
__global__ void k_hquant() {
    int m = blockIdx.x, tid = threadIdx.x;
    const float4* crow = reinterpret_cast<const float4*>(g_c1 + (size_t)m * DHIDDEN);
    float f = 1.0f / (g_xscale[m] * g_scales[0]);
    float gv[32];
    float amax = 0.0f;
    #pragma unroll
    for (int j = 0; j < 8; j++) {
        float4 v = crow[tid + j * 256];
        float a = gelu_exact(v.x * f), b = gelu_exact(v.y * f);
        float c = gelu_exact(v.z * f), d = gelu_exact(v.w * f);
        gv[j * 4 + 0] = a; gv[j * 4 + 1] = b; gv[j * 4 + 2] = c; gv[j * 4 + 3] = d;
        amax = fmaxf(amax, fmaxf(fmaxf(fabsf(a), fabsf(b)), fmaxf(fabsf(c), fabsf(d))));
    }
    float m8 = block_max_256(amax, tid);
    float scale = 127.0f / fmaxf(m8, EPSQ);
    uint2* orow = reinterpret_cast<uint2*>(g_hq + (size_t)m * DHIDDEN);
    #pragma unroll
    for (int j = 0; j < 8; j++) {
        uint2 o;
        o.x = pack_bf2(q_act(gv[j * 4 + 0], scale), q_act(gv[j * 4 + 1], scale));
        o.y = pack_bf2(q_act(gv[j * 4 + 2], scale), q_act(gv[j * 4 + 3], scale));
        orow[tid + j * 256] = o;
    }
    if (tid == 0) g_hscale[m] = scale;
}

// =================== bf16 GEMM: C = A(MxK) * B(NxK)^T (fp32 accum) ==========
// CTA tile 128x128, K-step 64 bf16 (128B rows, SW128 swizzle),
// cp.async 3-stage pipeline, 8 warps (4M x 2N), warp tile 32x64.
// (byte-for-byte the round-6 kernel — proven local optimum)
template <int KDIM, int MODE>
__global__ void __launch_bounds__(256, 2) k_gemm_bf(float* __restrict__ Cout) {
    constexpr int TM = 128, TN = 128, KSTEP = 64, STAGES = 3;
    constexpr int KT = KDIM / KSTEP;
    constexpr int TILE_BYTES = TM * 128;        // 16 KB (128 rows x 128B)

    extern __shared__ __align__(1024) char smem[];

    const __nv_bfloat16* __restrict__ A = (MODE == 0) ? g_xq  : g_hq;
    const __nv_bfloat16* __restrict__ B = (MODE == 0) ? g_w1q : g_w2q;

    const int tid = threadIdx.x, warp = tid >> 5, lane = tid & 31;
    const int mblock = blockIdx.y * TM;
    const int nblock = blockIdx.x * TN;
    const int wm = (warp >> 1) * 32;       // 4 warps along M
    const int wn = (warp & 1) * 64;        // 2 warps along N

    const uint32_t a_base = smem_u32(smem);
    const uint32_t b_base = a_base + STAGES * TILE_BYTES;

    // ldmatrix lane geometry (byte offsets within 128B-row tile)
    const int aRow = wm + (lane & 15);
    const int bRow = wn + (lane & 15);
    const int colB = (lane >> 4) * 16;     // 16B sub-column

    float acc[2][8][4];
    #pragma unroll
    for (int i = 0; i < 2; i++)
        #pragma unroll
        for (int j = 0; j < 8; j++)
            #pragma unroll
            for (int k = 0; k < 4; k++) acc[i][j][k] = 0.0f;

    // per-thread cp.async geometry: 1024 16B chunks per matrix per stage
    auto load_stage = [&](int kt, int buf) {
        #pragma unroll
        for (int i = 0; i < 4; i++) {
            int c = tid + i * 256;
            int row = c >> 3, ch = c & 7;
            uint32_t swo = SW((uint32_t)(row * 128 + ch * 16));
            const char* asrc = (const char*)A + (size_t)(mblock + row) * (KDIM * 2) + kt * 128 + ch * 16;
            const char* bsrc = (const char*)B + (size_t)(nblock + row) * (KDIM * 2) + kt * 128 + ch * 16;
            CP_ASYNC16(a_base + buf * TILE_BYTES + swo, asrc);
            CP_ASYNC16(b_base + buf * TILE_BYTES + swo, bsrc);
        }
    };

    // prologue: stages 0,1
    load_stage(0, 0); CP_COMMIT();
    load_stage(1, 1); CP_COMMIT();

    for (int kt = 0; kt < KT; kt++) {
        CP_WAIT(1);
        __syncthreads();

        const int nk = kt + 2;
        if (nk < KT) load_stage(nk, nk % STAGES);
        CP_COMMIT();

        const uint32_t abase = a_base + (kt % STAGES) * TILE_BYTES;
        const uint32_t bbase = b_base + (kt % STAGES) * TILE_BYTES;
        #pragma unroll
        for (int kk = 0; kk < 4; kk++) {           // 4 x K=16 per stage
            uint32_t af[2][4], bf[8][2];
            #pragma unroll
            for (int mt = 0; mt < 2; mt++)
                ldm_x4(af[mt], abase + SW((uint32_t)((aRow + mt * 16) * 128 + kk * 32 + colB)));
            #pragma unroll
            for (int p = 0; p < 4; p++) {          // each x4 covers 2 n-tiles
                uint32_t r[4];
                ldm_x4(r, bbase + SW((uint32_t)((bRow + p * 16) * 128 + kk * 32 + colB)));
                bf[p*2][0]   = r[0]; bf[p*2][1]   = r[2];
                bf[p*2+1][0] = r[1]; bf[p*2+1][1] = r[3];
            }
            #pragma unroll
            for (int mt = 0; mt < 2; mt++)
                #pragma unroll
                for (int nt = 0; nt < 8; nt++)
                    mma16816(acc[mt][nt], af[mt], bf[nt]);
        }
    }

    // ---- epilogue ----
    const int gq = lane >> 2;
    const int tc = (lane & 3) * 2;
    #pragma unroll
    for (int mt = 0; mt < 2; mt++) {
        const int m0 = mblock + wm + mt * 16 + gq;
        float inv0 = 1.0f, inv1 = 1.0f;
        if (MODE == 1) {
            inv0 = 1.0f / (g_hscale[m0]     * g_scales[1]);
            inv1 = 1.0f / (g_hscale[m0 + 8] * g_scales[1]);
        }
        #pragma unroll
        for (int nt = 0; nt < 8; nt++) {
            const int n0 = nblock + wn + nt * 8 + tc;
            if (MODE == 0) {
                float2 v0 = make_float2(acc[mt][nt][0], acc[mt][nt][1]);
                float2 v1 = make_float2(acc[mt][nt][2], acc[mt][nt][3]);
                *reinterpret_cast<float2*>(&g_c1[(size_t)m0 * DHIDDEN + n0])       = v0;
                *reinterpret_cast<float2*>(&g_c1[(size_t)(m0 + 8) * DHIDDEN + n0]) = v1;
            } else {
                float2 v0 = make_float2(acc[mt][nt][0] * inv0, acc[mt][nt][1] * inv0);
                float2 v1 = make_float2(acc[mt][nt][2] * inv1, acc[mt][nt][3] * inv1);
                *reinterpret_cast<float2*>(&Cout[(size_t)m0 * DMODEL + n0])       = v0;
                *reinterpret_cast<float2*>(&Cout[(size_t)(m0 + 8) * DMODEL + n0]) = v1;
            }
        }
    }
}

// ------------------------------- launch -------------------------------------
extern "C" void kernel_launch(void* const* d_in, const int* in_sizes, int n_in,
                              void* d_out, int out_size) {
    const float* x  = (const float*)d_in[0];
    const float* w1 = (const float*)d_in[1];
    const float* w2 = (const float*)d_in[2];
    float* out = (float*)d_out;

    constexpr int SMEM_BYTES = 3 * 2 * 128 * 128;   // 96 KB dynamic
    cudaFuncSetAttribute(k_gemm_bf<DMODEL, 0>,
                         cudaFuncAttributeMaxDynamicSharedMemorySize, SMEM_BYTES);
    cudaFuncSetAttribute(k_gemm_bf<DHIDDEN, 1>,
                         cudaFuncAttributeMaxDynamicSharedMemorySize, SMEM_BYTES);

    // One-time side stream + events (host handles only, reused every call).
    static cudaStream_t s1 = nullptr;
    static cudaEvent_t ev_fork = nullptr, ev_xq = nullptr, ev_w2 = nullptr;
    if (s1 == nullptr) {
        cudaStreamCreateWithFlags(&s1, cudaStreamNonBlocking);
        cudaEventCreateWithFlags(&ev_fork, cudaEventDisableTiming);
        cudaEventCreateWithFlags(&ev_xq,   cudaEventDisableTiming);
        cudaEventCreateWithFlags(&ev_w2,   cudaEventDisableTiming);
    }

    // side branch: xquant (independent), then the ENTIRE w2 chain — all of it
    // hides under the main branch's w1 chain + GEMM1.
    cudaEventRecord(ev_fork, 0);
    cudaStreamWaitEvent(s1, ev_fork, 0);
    k_xquant<<<TOKENS, 256, 0, s1>>>(x);
    cudaEventRecord(ev_xq, s1);
    k_wsum<1>  <<<2048, 256, 0, s1>>>(w2);
    k_scale<1> <<<1,    256, 0, s1>>>();
    k_wquant<1><<<8192, 256, 0, s1>>>(w2);
    cudaEventRecord(ev_w2, s1);

    // main branch: w1 chain only
    k_wsum<0>  <<<2048, 256>>>(w1);
    k_scale<0> <<<1,    256>>>();
    k_wquant<0><<<8192, 256>>>(w1);

    // join xquant, then GEMM1 -> hquant
    cudaStreamWaitEvent(0, ev_xq, 0);
    k_gemm_bf<DMODEL, 0><<<dim3(DHIDDEN / 128, TOKENS / 128), 256, SMEM_BYTES>>>(nullptr);
    k_hquant<<<TOKENS, 256>>>();

    // join w2 chain, then GEMM2
    cudaStreamWaitEvent(0, ev_w2, 0);
    k_gemm_bf<DHIDDEN, 1><<<dim3(DMODEL / 128, TOKENS / 128), 256, SMEM_BYTES>>>(out);
}

// round 17
// speedup vs baseline: 1.0273x; 1.0083x over previous
#include <cuda_runtime.h>
#include <cuda_bf16.h>
#include <cstdint>
#include <cstddef>

// ---------------------------------------------------------------------------
// BitNet FFN, round 17: round-16 kernels (proven best 1433.3us) + dependency
// narrowing on the w1 chain: w1 quantization split into row-halves; GEMM1
// split into matching n-halves running CONCURRENTLY on two streams (same
// total CTA footprint, no serialized tail). GEMM1 starts ~11us earlier.
// Arithmetic bit-identical (rel_err 5.973522e-4 expected unchanged).
// ---------------------------------------------------------------------------

#define EPSQ 1e-5f
#define TOKENS   8192
#define DMODEL   2048
#define DHIDDEN  8192

// ------------------------- device scratch (no allocs) ----------------------
__device__ float                        g_partial[4096];
__device__ float                        g_scales[2];
__device__ __align__(16) __nv_bfloat16  g_w1q[(size_t)DHIDDEN * DMODEL];
__device__ __align__(16) __nv_bfloat16  g_w2q[(size_t)DMODEL * DHIDDEN];
__device__ __align__(16) __nv_bfloat16  g_xq [(size_t)TOKENS * DMODEL];
__device__ float                        g_xscale[TOKENS];
__device__ __align__(16) float          g_c1 [(size_t)TOKENS * DHIDDEN];
__device__ __align__(16) __nv_bfloat16  g_hq [(size_t)TOKENS * DHIDDEN];
__device__ float                        g_hscale[TOKENS];

// ------------------------------- helpers -----------------------------------
__device__ __forceinline__ float gelu_exact(float v) {
    return 0.5f * v * (1.0f + erff(v * 0.70710678118654752440f));
}
__device__ __forceinline__ float q_act(float v, float s) {
    return fminf(fmaxf(rintf(v * s), -128.0f), 127.0f);
}
__device__ __forceinline__ float q_w(float v, float s) {
    return fminf(fmaxf(rintf(v * s), -1.0f), 1.0f);
}
__device__ __forceinline__ uint32_t pack_bf2(float a, float b) {
    __nv_bfloat162 h = __floats2bfloat162_rn(a, b);
    return *reinterpret_cast<uint32_t*>(&h);
}
__device__ __forceinline__ uint32_t smem_u32(const void* p) {
    return (uint32_t)__cvta_generic_to_shared(p);
}
__device__ __forceinline__ void ldm_x4(uint32_t* r, uint32_t addr) {
    asm volatile("ldmatrix.sync.aligned.m8n8.x4.shared.b16 {%0,%1,%2,%3}, [%4];"
                 : "=r"(r[0]), "=r"(r[1]), "=r"(r[2]), "=r"(r[3]) : "r"(addr));
}
__device__ __forceinline__ void mma16816(float* d, const uint32_t* a, const uint32_t* b) {
    asm volatile("mma.sync.aligned.m16n8k16.row.col.f32.bf16.bf16.f32 "
                 "{%0,%1,%2,%3}, {%4,%5,%6,%7}, {%8,%9}, {%0,%1,%2,%3};"
                 : "+f"(d[0]), "+f"(d[1]), "+f"(d[2]), "+f"(d[3])
                 : "r"(a[0]), "r"(a[1]), "r"(a[2]), "r"(a[3]),
                   "r"(b[0]), "r"(b[1]));
}
#define CP_ASYNC16(dst, src) \
    asm volatile("cp.async.cg.shared.global [%0], [%1], 16;" :: "r"(dst), "l"(src) : "memory")
#define CP_COMMIT() asm volatile("cp.async.commit_group;" ::: "memory")
#define CP_WAIT(n)  asm volatile("cp.async.wait_group %0;" :: "n"(n) : "memory")
// SW128 swizzle on byte offset within a 128B-row tile (Swizzle<3,4,3>)
#define SW(o) ((o) ^ (((o) >> 3) & 0x70))

// warp-level reductions (max is order-independent -> bit-exact)
__device__ __forceinline__ float warp_max(float v) {
    #pragma unroll
    for (int o = 16; o > 0; o >>= 1)
        v = fmaxf(v, __shfl_xor_sync(0xffffffffu, v, o));
    return v;
}
__device__ __forceinline__ float warp_sum(float v) {
    #pragma unroll
    for (int o = 16; o > 0; o >>= 1)
        v += __shfl_xor_sync(0xffffffffu, v, o);
    return v;
}
// 256-thread block max with a single barrier
__device__ __forceinline__ float block_max_256(float v, int tid) {
    __shared__ float wred[8];
    float wm = warp_max(v);
    if ((tid & 31) == 0) wred[tid >> 5] = wm;
    __syncthreads();
    float m = wred[0];
    #pragma unroll
    for (int i = 1; i < 8; i++) m = fmaxf(m, wred[i]);
    return m;
}

// -------------- K0: |w| partial sums for ONE matrix (float4) ----------------
template <int IDX>
__global__ void k_wsum(const float* __restrict__ w) {
    int b = blockIdx.x;
    const float4* wv = reinterpret_cast<const float4*>(w + (size_t)b * 8192);
    float s = 0.0f;
    #pragma unroll
    for (int i = 0; i < 8; i++) {
        float4 v = wv[threadIdx.x + i * 256];
        s += fabsf(v.x) + fabsf(v.y) + fabsf(v.z) + fabsf(v.w);
    }
    __shared__ float wred[8];
    float ws = warp_sum(s);
    if ((threadIdx.x & 31) == 0) wred[threadIdx.x >> 5] = ws;
    __syncthreads();
    if (threadIdx.x == 0) {
        float t = wred[0];
        #pragma unroll
        for (int i = 1; i < 8; i++) t += wred[i];
        g_partial[IDX * 2048 + b] = t;
    }
}

// -------------- K0b: finalize scale for ONE matrix --------------------------
template <int IDX>
__global__ void k_scale() {
    __shared__ float red[256];
    float s = 0.0f;
    for (int i = threadIdx.x; i < 2048; i += 256) s += g_partial[IDX * 2048 + i];
    red[threadIdx.x] = s; __syncthreads();
    for (int o = 128; o > 0; o >>= 1) {
        if (threadIdx.x < o) red[threadIdx.x] += red[threadIdx.x + o];
        __syncthreads();
    }
    if (threadIdx.x == 0) {
        float m = red[0] * (1.0f / 16777216.0f);
        g_scales[IDX] = 1.0f / fmaxf(m, EPSQ);
    }
}

// ---------------- K1: ternary-quantize rows [boff, boff+grid) of one matrix -
// One block = one 2048-element row chunk (8 elems/thread), same as round 16.
template <int IDX>
__global__ void k_wquant(const float* __restrict__ w, int boff) {
    __nv_bfloat16* o = (IDX == 0) ? g_w1q : g_w2q;
    float s = g_scales[IDX];
    size_t idx = ((size_t)(blockIdx.x + boff) * 256 + threadIdx.x) * 8;
    float4 v0 = *reinterpret_cast<const float4*>(w + idx);
    float4 v1 = *reinterpret_cast<const float4*>(w + idx + 4);
    uint4 out;
    out.x = pack_bf2(q_w(v0.x, s), q_w(v0.y, s));
    out.y = pack_bf2(q_w(v0.z, s), q_w(v0.w, s));
    out.z = pack_bf2(q_w(v1.x, s), q_w(v1.y, s));
    out.w = pack_bf2(q_w(v1.z, s), q_w(v1.w, s));
    *reinterpret_cast<uint4*>(o + idx) = out;
}

// ------------------------- K2: per-token int8 quant of x --------------------
__global__ void k_xquant(const float* __restrict__ x) {
    int m = blockIdx.x, tid = threadIdx.x;
    const float4* row = reinterpret_cast<const float4*>(x + (size_t)m * DMODEL);
    float4 v0 = row[tid], v1 = row[tid + 256];
    float amax = fmaxf(fmaxf(fmaxf(fabsf(v0.x), fabsf(v0.y)), fmaxf(fabsf(v0.z), fabsf(v0.w))),
                       fmaxf(fmaxf(fabsf(v1.x), fabsf(v1.y)), fmaxf(fabsf(v1.z), fabsf(v1.w))));
    float m8 = block_max_256(amax, tid);
    float scale = 127.0f / fmaxf(m8, EPSQ);
    uint2 o0, o1;
    o0.x = pack_bf2(q_act(v0.x, scale), q_act(v0.y, scale));
    o0.y = pack_bf2(q_act(v0.z, scale), q_act(v0.w, scale));
    o1.x = pack_bf2(q_act(v1.x, scale), q_act(v1.y, scale));
    o1.y = pack_bf2(q_act(v1.z, scale), q_act(v1.w, scale));
    uint2* orow = reinterpret_cast<uint2*>(g_xq + (size_t)m * DMODEL);
    orow[tid] = o0;
    orow[tid + 256] = o1;
    if (tid == 0) g_xscale[m] = scale;
}

// ------------------------- K4: dequant + gelu + row requant -----------------
__global__ void k_hquant() {
    int m = blockIdx.x, tid = threadIdx.x;
    const float4* crow = reinterpret_cast<const float4*>(g_c1 + (size_t)m * DHIDDEN);
    float f = 1.0f / (g_xscale[m] * g_scales[0]);
    float gv[32];
    float amax = 0.0f;
    #pragma unroll
    for (int j = 0; j < 8; j++) {
        float4 v = crow[tid + j * 256];
        float a = gelu_exact(v.x * f), b = gelu_exact(v.y * f);
        float c = gelu_exact(v.z * f), d = gelu_exact(v.w * f);
        gv[j * 4 + 0] = a; gv[j * 4 + 1] = b; gv[j * 4 + 2] = c; gv[j * 4 + 3] = d;
        amax = fmaxf(amax, fmaxf(fmaxf(fabsf(a), fabsf(b)), fmaxf(fabsf(c), fabsf(d))));
    }
    float m8 = block_max_256(amax, tid);
    float scale = 127.0f / fmaxf(m8, EPSQ);
    uint2* orow = reinterpret_cast<uint2*>(g_hq + (size_t)m * DHIDDEN);
    #pragma unroll
    for (int j = 0; j < 8; j++) {
        uint2 o;
        o.x = pack_bf2(q_act(gv[j * 4 + 0], scale), q_act(gv[j * 4 + 1], scale));
        o.y = pack_bf2(q_act(gv[j * 4 + 2], scale), q_act(gv[j * 4 + 3], scale));
        orow[tid + j * 256] = o;
    }
    if (tid == 0) g_hscale[m] = scale;
}

// =================== bf16 GEMM: C = A(MxK) * B(NxK)^T (fp32 accum) ==========
// CTA tile 128x128, K-step 64 bf16 (128B rows, SW128 swizzle),
// cp.async 3-stage pipeline, 8 warps (4M x 2N), warp tile 32x64.
// noff: n-tile offset (units of 128 cols) so GEMM1 can launch in n-halves.
template <int KDIM, int MODE>
__global__ void __launch_bounds__(256, 2) k_gemm_bf(float* __restrict__ Cout, int noff) {
    constexpr int TM = 128, TN = 128, KSTEP = 64, STAGES = 3;
    constexpr int KT = KDIM / KSTEP;
    constexpr int TILE_BYTES = TM * 128;        // 16 KB (128 rows x 128B)

    extern __shared__ __align__(1024) char smem[];

    const __nv_bfloat16* __restrict__ A = (MODE == 0) ? g_xq  : g_hq;
    const __nv_bfloat16* __restrict__ B = (MODE == 0) ? g_w1q : g_w2q;

    const int tid = threadIdx.x, warp = tid >> 5, lane = tid & 31;
    const int mblock = blockIdx.y * TM;
    const int nblock = (blockIdx.x + noff) * TN;
    const int wm = (warp >> 1) * 32;       // 4 warps along M
    const int wn = (warp & 1) * 64;        // 2 warps along N

    const uint32_t a_base = smem_u32(smem);
    const uint32_t b_base = a_base + STAGES * TILE_BYTES;

    // ldmatrix lane geometry (byte offsets within 128B-row tile)
    const int aRow = wm + (lane & 15);
    const int bRow = wn + (lane & 15);
    const int colB = (lane >> 4) * 16;     // 16B sub-column

    float acc[2][8][4];
    #pragma unroll
    for (int i = 0; i < 2; i++)
        #pragma unroll
        for (int j = 0; j < 8; j++)
            #pragma unroll
            for (int k = 0; k < 4; k++) acc[i][j][k] = 0.0f;

    // per-thread cp.async geometry: 1024 16B chunks per matrix per stage
    auto load_stage = [&](int kt, int buf) {
        #pragma unroll
        for (int i = 0; i < 4; i++) {
            int c = tid + i * 256;
            int row = c >> 3, ch = c & 7;
            uint32_t swo = SW((uint32_t)(row * 128 + ch * 16));
            const char* asrc = (const char*)A + (size_t)(mblock + row) * (KDIM * 2) + kt * 128 + ch * 16;
            const char* bsrc = (const char*)B + (size_t)(nblock + row) * (KDIM * 2) + kt * 128 + ch * 16;
            CP_ASYNC16(a_base + buf * TILE_BYTES + swo, asrc);
            CP_ASYNC16(b_base + buf * TILE_BYTES + swo, bsrc);
        }
    };

    // prologue: stages 0,1
    load_stage(0, 0); CP_COMMIT();
    load_stage(1, 1); CP_COMMIT();

    for (int kt = 0; kt < KT; kt++) {
        CP_WAIT(1);
        __syncthreads();

        const int nk = kt + 2;
        if (nk < KT) load_stage(nk, nk % STAGES);
        CP_COMMIT();

        const uint32_t abase = a_base + (kt % STAGES) * TILE_BYTES;
        const uint32_t bbase = b_base + (kt % STAGES) * TILE_BYTES;
        #pragma unroll
        for (int kk = 0; kk < 4; kk++) {           // 4 x K=16 per stage
            uint32_t af[2][4], bf[8][2];
            #pragma unroll
            for (int mt = 0; mt < 2; mt++)
                ldm_x4(af[mt], abase + SW((uint32_t)((aRow + mt * 16) * 128 + kk * 32 + colB)));
            #pragma unroll
            for (int p = 0; p < 4; p++) {          // each x4 covers 2 n-tiles
                uint32_t r[4];
                ldm_x4(r, bbase + SW((uint32_t)((bRow + p * 16) * 128 + kk * 32 + colB)));
                bf[p*2][0]   = r[0]; bf[p*2][1]   = r[2];
                bf[p*2+1][0] = r[1]; bf[p*2+1][1] = r[3];
            }
            #pragma unroll
            for (int mt = 0; mt < 2; mt++)
                #pragma unroll
                for (int nt = 0; nt < 8; nt++)
                    mma16816(acc[mt][nt], af[mt], bf[nt]);
        }
    }

    // ---- epilogue ----
    const int gq = lane >> 2;
    const int tc = (lane & 3) * 2;
    #pragma unroll
    for (int mt = 0; mt < 2; mt++) {
        const int m0 = mblock + wm + mt * 16 + gq;
        float inv0 = 1.0f, inv1 = 1.0f;
        if (MODE == 1) {
            inv0 = 1.0f / (g_hscale[m0]     * g_scales[1]);
            inv1 = 1.0f / (g_hscale[m0 + 8] * g_scales[1]);
        }
        #pragma unroll
        for (int nt = 0; nt < 8; nt++) {
            const int n0 = nblock + wn + nt * 8 + tc;
            if (MODE == 0) {
                float2 v0 = make_float2(acc[mt][nt][0], acc[mt][nt][1]);
                float2 v1 = make_float2(acc[mt][nt][2], acc[mt][nt][3]);
                *reinterpret_cast<float2*>(&g_c1[(size_t)m0 * DHIDDEN + n0])       = v0;
                *reinterpret_cast<float2*>(&g_c1[(size_t)(m0 + 8) * DHIDDEN + n0]) = v1;
            } else {
                float2 v0 = make_float2(acc[mt][nt][0] * inv0, acc[mt][nt][1] * inv0);
                float2 v1 = make_float2(acc[mt][nt][2] * inv1, acc[mt][nt][3] * inv1);
                *reinterpret_cast<float2*>(&Cout[(size_t)m0 * DMODEL + n0])       = v0;
                *reinterpret_cast<float2*>(&Cout[(size_t)(m0 + 8) * DMODEL + n0]) = v1;
            }
        }
    }
}

// ------------------------------- launch -------------------------------------
extern "C" void kernel_launch(void* const* d_in, const int* in_sizes, int n_in,
                              void* d_out, int out_size) {
    const float* x  = (const float*)d_in[0];
    const float* w1 = (const float*)d_in[1];
    const float* w2 = (const float*)d_in[2];
    float* out = (float*)d_out;

    constexpr int SMEM_BYTES = 3 * 2 * 128 * 128;   // 96 KB dynamic
    cudaFuncSetAttribute(k_gemm_bf<DMODEL, 0>,
                         cudaFuncAttributeMaxDynamicSharedMemorySize, SMEM_BYTES);
    cudaFuncSetAttribute(k_gemm_bf<DHIDDEN, 1>,
                         cudaFuncAttributeMaxDynamicSharedMemorySize, SMEM_BYTES);

    // One-time side streams + events (host handles only, reused every call).
    static cudaStream_t s1 = nullptr, s2 = nullptr;
    static cudaEvent_t ev_fork = nullptr, ev_xq = nullptr, ev_s0 = nullptr,
                       ev_w0b = nullptr, ev_g1b = nullptr, ev_w2 = nullptr;
    if (s1 == nullptr) {
        cudaStreamCreateWithFlags(&s1, cudaStreamNonBlocking);
        cudaStreamCreateWithFlags(&s2, cudaStreamNonBlocking);
        cudaEventCreateWithFlags(&ev_fork, cudaEventDisableTiming);
        cudaEventCreateWithFlags(&ev_xq,   cudaEventDisableTiming);
        cudaEventCreateWithFlags(&ev_s0,   cudaEventDisableTiming);
        cudaEventCreateWithFlags(&ev_w0b,  cudaEventDisableTiming);
        cudaEventCreateWithFlags(&ev_g1b,  cudaEventDisableTiming);
        cudaEventCreateWithFlags(&ev_w2,   cudaEventDisableTiming);
    }

    cudaEventRecord(ev_fork, 0);
    cudaStreamWaitEvent(s1, ev_fork, 0);
    cudaStreamWaitEvent(s2, ev_fork, 0);

    // s1: xquant (independent of all weight work)
    k_xquant<<<TOKENS, 256, 0, s1>>>(x);
    cudaEventRecord(ev_xq, s1);

    // main: w1 scale chain, then quantize HALF A of w1 (rows 0..4095)
    k_wsum<0>  <<<2048, 256>>>(w1);
    k_scale<0> <<<1,    256>>>();
    cudaEventRecord(ev_s0, 0);
    k_wquant<0><<<4096, 256>>>(w1, 0);

    // s1: after scale0 — quantize HALF B of w1 (rows 4096..8191), then w2 chain
    cudaStreamWaitEvent(s1, ev_s0, 0);
    k_wquant<0><<<4096, 256, 0, s1>>>(w1, 4096);
    cudaEventRecord(ev_w0b, s1);
    k_wsum<1>  <<<2048, 256, 0, s1>>>(w2);
    k_scale<1> <<<1,    256, 0, s1>>>();
    k_wquant<1><<<8192, 256, 0, s1>>>(w2, 0);
    cudaEventRecord(ev_w2, s1);

    // GEMM1 halves run CONCURRENTLY (n-tiles 0..31 on main, 32..63 on s2)
    cudaStreamWaitEvent(0, ev_xq, 0);
    k_gemm_bf<DMODEL, 0><<<dim3(32, TOKENS / 128), 256, SMEM_BYTES>>>(nullptr, 0);
    cudaStreamWaitEvent(s2, ev_xq, 0);
    cudaStreamWaitEvent(s2, ev_w0b, 0);
    k_gemm_bf<DMODEL, 0><<<dim3(32, TOKENS / 128), 256, SMEM_BYTES, s2>>>(nullptr, 32);
    cudaEventRecord(ev_g1b, s2);

    // hquant after BOTH GEMM1 halves
    cudaStreamWaitEvent(0, ev_g1b, 0);
    k_hquant<<<TOKENS, 256>>>();

    // GEMM2 after hquant + w2 chain
    cudaStreamWaitEvent(0, ev_w2, 0);
    k_gemm_bf<DHIDDEN, 1><<<dim3(DMODEL / 128, TOKENS / 128), 256, SMEM_BYTES>>>(out, 0);
}